// round 1
// baseline (speedup 1.0000x reference)
#include <cuda_runtime.h>

// Problem constants
constexpr int B  = 4;      // batch
constexpr int C  = 512;    // channels
constexpr int T  = 3;      // temporal frames
constexpr int HW = 2304;   // 48*48
constexpr int N3 = 6912;   // 3*HW
constexpr int G  = 4;      // norm groups
constexpr int CG = C / G;  // 128
constexpr float EPS = 1e-6f;

// Scratch (static device allocations are allowed)
__device__ float g_hn[(size_t)B * C * T * HW];   // normalized activations [b][c][t][p]
__device__ float g_q [(size_t)B * C * HW];       // q (t=1) / skip
__device__ float g_k [(size_t)B * C * N3];
__device__ float g_v [(size_t)B * C * N3];
__device__ float g_sc[(size_t)B * HW * N3];      // scores / attn (255 MB)
__device__ float g_ao[(size_t)B * C * HW];       // attention output
__device__ float g_stats[2 * B * G];             // sum, sumsq per (b,g)

// ---------------------------------------------------------------------------
// GroupNorm stats
// ---------------------------------------------------------------------------
__global__ void zero_stats_kernel() {
    if (threadIdx.x < 2 * B * G) g_stats[threadIdx.x] = 0.f;
}

__global__ void gn_stats_kernel(const float* __restrict__ x) {
    const int bg = blockIdx.x;              // 16 groups
    const int b = bg >> 2, g = bg & 3;
    const int TOT4 = CG * T * HW / 4;       // 221184 float4 per group
    const int PER  = TOT4 / 16;             // per-slice
    const int start = blockIdx.y * PER;

    float s = 0.f, ss = 0.f;
    for (int i = start + threadIdx.x; i < start + PER; i += blockDim.x) {
        int cl = i / (T * HW / 4);
        int r  = i - cl * (T * HW / 4);
        int t  = r / (HW / 4);
        int p4 = r - t * (HW / 4);
        float4 v = reinterpret_cast<const float4*>(x)[
            ((size_t)(t * B + b) * C + g * CG + cl) * (HW / 4) + p4];
        s  += v.x + v.y + v.z + v.w;
        ss += v.x * v.x + v.y * v.y + v.z * v.z + v.w * v.w;
    }
    __shared__ float rs[8], rss[8];
    #pragma unroll
    for (int o = 16; o; o >>= 1) {
        s  += __shfl_xor_sync(0xffffffffu, s, o);
        ss += __shfl_xor_sync(0xffffffffu, ss, o);
    }
    if ((threadIdx.x & 31) == 0) { rs[threadIdx.x >> 5] = s; rss[threadIdx.x >> 5] = ss; }
    __syncthreads();
    if (threadIdx.x == 0) {
        float a = 0.f, c = 0.f;
        #pragma unroll
        for (int i = 0; i < 8; i++) { a += rs[i]; c += rss[i]; }
        atomicAdd(&g_stats[2 * bg],     a);
        atomicAdd(&g_stats[2 * bg + 1], c);
    }
}

// normalize + affine -> g_hn[b][c][t][p]
__global__ void gn_apply_kernel(const float* __restrict__ x,
                                const float* __restrict__ scale,
                                const float* __restrict__ bias) {
    int i = blockIdx.x * blockDim.x + threadIdx.x;   // float4 index over B*C*T*HW/4
    int p4 = i % (HW / 4);
    int r  = i / (HW / 4);
    int t  = r % T;  r /= T;
    int c  = r % C;
    int b  = r / C;
    int g  = c / CG;

    const float n = (float)(CG * T * HW);
    float sum = g_stats[2 * (b * G + g)];
    float sq  = g_stats[2 * (b * G + g) + 1];
    float mean = sum / n;
    float var  = sq / n - mean * mean;
    float rstd = rsqrtf(var + EPS);
    float a = rstd * scale[c];
    float d = bias[c] - mean * a;

    float4 v = reinterpret_cast<const float4*>(x)[((size_t)(t * B + b) * C + c) * (HW / 4) + p4];
    float4 o = make_float4(v.x * a + d, v.y * a + d, v.z * a + d, v.w * a + d);
    reinterpret_cast<float4*>(g_hn)[i] = o;
}

// ---------------------------------------------------------------------------
// SGEMM: C[m,n] = alpha * sum_k A'(k,m) * B'(k,n) (+ bias[m]) (+ skip[m,n])
// TA/TB: operand stored [X][K] (transposed load) vs [K][X] (direct load).
// 128x128 tile, BK=8, 256 threads, 8x8 microtile, double-buffered smem.
// All dims must divide evenly (they do for this problem).
// ---------------------------------------------------------------------------
template <bool TA, bool TB, bool HAS_BIAS, bool HAS_SKIP>
__global__ __launch_bounds__(256, 2)
void sgemm_kernel(const float* __restrict__ A, int lda, long long sA,
                  const float* __restrict__ Bm, int ldb, long long sB,
                  float* __restrict__ Cm, int ldc, long long sC,
                  int K, float alpha,
                  const float* __restrict__ bias,
                  const float* __restrict__ skip, int ldsk, long long sSk) {
    const int bz = blockIdx.z;
    A  += (size_t)bz * sA;
    Bm += (size_t)bz * sB;
    Cm += (size_t)bz * sC;
    if (HAS_SKIP) skip += (size_t)bz * sSk;

    const int bm = blockIdx.x * 128, bn = blockIdx.y * 128;
    __shared__ float As[2][8][128];
    __shared__ float Bs[2][8][128];
    const int tid = threadIdx.x;

    const int dkr = tid >> 5, dm4 = (tid & 31) << 2;  // direct:   k-row, m-col*4
    const int tm  = tid >> 1, tkq = (tid & 1) << 2;   // trans:    m-row, k-col*4

    float acc[8][8];
    #pragma unroll
    for (int i = 0; i < 8; i++)
        #pragma unroll
        for (int j = 0; j < 8; j++) acc[i][j] = 0.f;

    auto ldgA = [&](int k0) -> float4 {
        if (TA) return *reinterpret_cast<const float4*>(&A[(size_t)(bm + tm) * lda + k0 + tkq]);
        else    return *reinterpret_cast<const float4*>(&A[(size_t)(k0 + dkr) * lda + bm + dm4]);
    };
    auto ldgB = [&](int k0) -> float4 {
        if (TB) return *reinterpret_cast<const float4*>(&Bm[(size_t)(bn + tm) * ldb + k0 + tkq]);
        else    return *reinterpret_cast<const float4*>(&Bm[(size_t)(k0 + dkr) * ldb + bn + dm4]);
    };
    auto stsA = [&](float4 v, int buf) {
        if (TA) {
            As[buf][tkq + 0][tm] = v.x; As[buf][tkq + 1][tm] = v.y;
            As[buf][tkq + 2][tm] = v.z; As[buf][tkq + 3][tm] = v.w;
        } else {
            *reinterpret_cast<float4*>(&As[buf][dkr][dm4]) = v;
        }
    };
    auto stsB = [&](float4 v, int buf) {
        if (TB) {
            Bs[buf][tkq + 0][tm] = v.x; Bs[buf][tkq + 1][tm] = v.y;
            Bs[buf][tkq + 2][tm] = v.z; Bs[buf][tkq + 3][tm] = v.w;
        } else {
            *reinterpret_cast<float4*>(&Bs[buf][dkr][dm4]) = v;
        }
    };

    float4 pa = ldgA(0), pb = ldgB(0);
    stsA(pa, 0); stsB(pb, 0);
    __syncthreads();

    const int nk = K >> 3;
    const int tx = tid & 15, ty = tid >> 4;
    for (int kt = 0; kt < nk; kt++) {
        const int cur = kt & 1;
        const bool pre = (kt + 1 < nk);
        if (pre) { pa = ldgA((kt + 1) << 3); pb = ldgB((kt + 1) << 3); }
        #pragma unroll
        for (int k = 0; k < 8; k++) {
            float4 a0 = *reinterpret_cast<const float4*>(&As[cur][k][ty << 2]);
            float4 a1 = *reinterpret_cast<const float4*>(&As[cur][k][64 + (ty << 2)]);
            float4 b0 = *reinterpret_cast<const float4*>(&Bs[cur][k][tx << 2]);
            float4 b1 = *reinterpret_cast<const float4*>(&Bs[cur][k][64 + (tx << 2)]);
            float av[8] = {a0.x, a0.y, a0.z, a0.w, a1.x, a1.y, a1.z, a1.w};
            float bv[8] = {b0.x, b0.y, b0.z, b0.w, b1.x, b1.y, b1.z, b1.w};
            #pragma unroll
            for (int i = 0; i < 8; i++)
                #pragma unroll
                for (int j = 0; j < 8; j++)
                    acc[i][j] = fmaf(av[i], bv[j], acc[i][j]);
        }
        if (pre) { stsA(pa, cur ^ 1); stsB(pb, cur ^ 1); }
        __syncthreads();
    }

    #pragma unroll
    for (int i = 0; i < 8; i++) {
        int row = bm + ((i < 4) ? (ty * 4 + i) : (64 + ty * 4 + i - 4));
        float bvv = HAS_BIAS ? bias[row] : 0.f;
        #pragma unroll
        for (int jh = 0; jh < 2; jh++) {
            int col = bn + jh * 64 + tx * 4;
            float4 o;
            o.x = fmaf(acc[i][jh * 4 + 0], alpha, bvv);
            o.y = fmaf(acc[i][jh * 4 + 1], alpha, bvv);
            o.z = fmaf(acc[i][jh * 4 + 2], alpha, bvv);
            o.w = fmaf(acc[i][jh * 4 + 3], alpha, bvv);
            if (HAS_SKIP) {
                float4 s = *reinterpret_cast<const float4*>(&skip[(size_t)row * ldsk + col]);
                o.x += s.x; o.y += s.y; o.z += s.z; o.w += s.w;
            }
            *reinterpret_cast<float4*>(&Cm[(size_t)row * ldc + col]) = o;
        }
    }
}

// ---------------------------------------------------------------------------
// Row softmax over 6912 elements; one block per row, values kept in registers.
// ---------------------------------------------------------------------------
__global__ void softmax_kernel(float* __restrict__ sc) {
    __shared__ float red[8];
    __shared__ float bmax, bsum;
    const int tid = threadIdx.x;
    float* row = sc + (size_t)blockIdx.x * N3;

    float vals[27];
    float mx = -1e30f;
    #pragma unroll
    for (int i = 0; i < 27; i++) {
        vals[i] = row[i * 256 + tid];
        mx = fmaxf(mx, vals[i]);
    }
    #pragma unroll
    for (int o = 16; o; o >>= 1) mx = fmaxf(mx, __shfl_xor_sync(0xffffffffu, mx, o));
    if ((tid & 31) == 0) red[tid >> 5] = mx;
    __syncthreads();
    if (tid < 32) {
        float t = (tid < 8) ? red[tid] : -1e30f;
        #pragma unroll
        for (int o = 4; o; o >>= 1) t = fmaxf(t, __shfl_xor_sync(0xffffffffu, t, o));
        if (tid == 0) bmax = t;
    }
    __syncthreads();
    mx = bmax;

    float s = 0.f;
    #pragma unroll
    for (int i = 0; i < 27; i++) { vals[i] = __expf(vals[i] - mx); s += vals[i]; }
    #pragma unroll
    for (int o = 16; o; o >>= 1) s += __shfl_xor_sync(0xffffffffu, s, o);
    if ((tid & 31) == 0) red[tid >> 5] = s;
    __syncthreads();
    if (tid < 32) {
        float t = (tid < 8) ? red[tid] : 0.f;
        #pragma unroll
        for (int o = 4; o; o >>= 1) t += __shfl_xor_sync(0xffffffffu, t, o);
        if (tid == 0) bsum = t;
    }
    __syncthreads();
    float inv = 1.f / bsum;
    #pragma unroll
    for (int i = 0; i < 27; i++) row[i * 256 + tid] = vals[i] * inv;
}

// ---------------------------------------------------------------------------
// Launch
// ---------------------------------------------------------------------------
extern "C" void kernel_launch(void* const* d_in, const int* in_sizes, int n_in,
                              void* d_out, int out_size) {
    const float* x   = (const float*)d_in[0];
    const float* nsc = (const float*)d_in[1];
    const float* nbi = (const float*)d_in[2];
    const float* q_w = (const float*)d_in[3];
    const float* q_b = (const float*)d_in[4];
    const float* k_w = (const float*)d_in[5];
    const float* k_b = (const float*)d_in[6];
    const float* v_w = (const float*)d_in[7];
    const float* v_b = (const float*)d_in[8];
    const float* p_w = (const float*)d_in[9];
    const float* p_b = (const float*)d_in[10];
    float* out = (float*)d_out;

    float *hn, *q, *k, *v, *sc, *ao;
    cudaGetSymbolAddress((void**)&hn, g_hn);
    cudaGetSymbolAddress((void**)&q,  g_q);
    cudaGetSymbolAddress((void**)&k,  g_k);
    cudaGetSymbolAddress((void**)&v,  g_v);
    cudaGetSymbolAddress((void**)&sc, g_sc);
    cudaGetSymbolAddress((void**)&ao, g_ao);

    // GroupNorm
    zero_stats_kernel<<<1, 32>>>();
    gn_stats_kernel<<<dim3(B * G, 16), 256>>>(x);
    gn_apply_kernel<<<(B * C * T * HW / 4) / 256, 256>>>(x, nsc, nbi);

    const long long sHn = (long long)C * N3;   // per-batch stride of hn
    const long long sKV = (long long)C * N3;
    const long long sQ  = (long long)C * HW;
    const long long sSc = (long long)HW * N3;

    // k = k_w @ hn + k_b     (o x 6912 per batch)
    sgemm_kernel<true, false, true, false><<<dim3(C / 128, N3 / 128, B), 256>>>(
        k_w, C, 0, hn, N3, sHn, k, N3, sKV, C, 1.f, k_b, nullptr, 0, 0);
    // v = v_w @ hn + v_b
    sgemm_kernel<true, false, true, false><<<dim3(C / 128, N3 / 128, B), 256>>>(
        v_w, C, 0, hn, N3, sHn, v, N3, sKV, C, 1.f, v_b, nullptr, 0, 0);
    // q = q_w @ hn[:, :, t=1] + q_b   (o x 2304 per batch); also serves as skip
    sgemm_kernel<true, false, true, false><<<dim3(C / 128, HW / 128, B), 256>>>(
        q_w, C, 0, hn + HW, N3, sHn, q, HW, sQ, C, 1.f, q_b, nullptr, 0, 0);

    // scores = (q^T k) * C^-0.5   (2304 x 6912 per batch)
    sgemm_kernel<false, false, false, false><<<dim3(HW / 128, N3 / 128, B), 256>>>(
        q, HW, sQ, k, N3, sKV, sc, N3, sSc, C, 0.044194173824159216f,
        nullptr, nullptr, 0, 0);

    softmax_kernel<<<B * HW, 256>>>(sc);

    // ao = v @ attn^T   (512 x 2304 per batch, K = 6912)
    sgemm_kernel<true, true, false, false><<<dim3(C / 128, HW / 128, B), 256>>>(
        v, N3, sKV, sc, N3, sSc, ao, HW, sQ, N3, 1.f, nullptr, nullptr, 0, 0);

    // out = p_w @ ao + p_b + skip(q)
    sgemm_kernel<true, false, true, true><<<dim3(C / 128, HW / 128, B), 256>>>(
        p_w, C, 0, ao, HW, sQ, out, HW, sQ, C, 1.f, p_b, q, HW, sQ);
}

// round 2
// speedup vs baseline: 1.0016x; 1.0016x over previous
#include <cuda_runtime.h>

// Problem constants
constexpr int B  = 4;      // batch
constexpr int C  = 512;    // channels
constexpr int T  = 3;      // temporal frames
constexpr int HW = 2304;   // 48*48
constexpr int N3 = 6912;   // 3*HW
constexpr int G  = 4;      // norm groups
constexpr int CG = C / G;  // 128
constexpr float EPS = 1e-6f;

// Scratch (static device allocations are allowed)
__device__ float g_hn[(size_t)B * C * T * HW];   // normalized activations [b][c][t][p]
__device__ float g_q [(size_t)B * C * HW];       // q (t=1) / skip
__device__ float g_k [(size_t)B * C * N3];
__device__ float g_v [(size_t)B * C * N3];
__device__ float g_sc[(size_t)B * HW * N3];      // scores / attn (255 MB)
__device__ float g_ao[(size_t)B * C * HW];       // attention output
__device__ float g_stats[2 * B * G];             // sum, sumsq per (b,g)

// ---------------------------------------------------------------------------
// GroupNorm stats
// ---------------------------------------------------------------------------
__global__ void zero_stats_kernel() {
    if (threadIdx.x < 2 * B * G) g_stats[threadIdx.x] = 0.f;
}

__global__ void gn_stats_kernel(const float* __restrict__ x) {
    const int bg = blockIdx.x;              // 16 groups
    const int b = bg >> 2, g = bg & 3;
    const int TOT4 = CG * T * HW / 4;       // 221184 float4 per group
    const int PER  = TOT4 / 16;             // per-slice
    const int start = blockIdx.y * PER;

    float s = 0.f, ss = 0.f;
    for (int i = start + threadIdx.x; i < start + PER; i += blockDim.x) {
        int cl = i / (T * HW / 4);
        int r  = i - cl * (T * HW / 4);
        int t  = r / (HW / 4);
        int p4 = r - t * (HW / 4);
        float4 v = reinterpret_cast<const float4*>(x)[
            ((size_t)(t * B + b) * C + g * CG + cl) * (HW / 4) + p4];
        s  += v.x + v.y + v.z + v.w;
        ss += v.x * v.x + v.y * v.y + v.z * v.z + v.w * v.w;
    }
    __shared__ float rs[8], rss[8];
    #pragma unroll
    for (int o = 16; o; o >>= 1) {
        s  += __shfl_xor_sync(0xffffffffu, s, o);
        ss += __shfl_xor_sync(0xffffffffu, ss, o);
    }
    if ((threadIdx.x & 31) == 0) { rs[threadIdx.x >> 5] = s; rss[threadIdx.x >> 5] = ss; }
    __syncthreads();
    if (threadIdx.x == 0) {
        float a = 0.f, c = 0.f;
        #pragma unroll
        for (int i = 0; i < 8; i++) { a += rs[i]; c += rss[i]; }
        atomicAdd(&g_stats[2 * bg],     a);
        atomicAdd(&g_stats[2 * bg + 1], c);
    }
}

// normalize + affine -> g_hn[b][c][t][p]
__global__ void gn_apply_kernel(const float* __restrict__ x,
                                const float* __restrict__ scale,
                                const float* __restrict__ bias) {
    int i = blockIdx.x * blockDim.x + threadIdx.x;   // float4 index over B*C*T*HW/4
    int p4 = i % (HW / 4);
    int r  = i / (HW / 4);
    int t  = r % T;  r /= T;
    int c  = r % C;
    int b  = r / C;
    int g  = c / CG;

    const float n = (float)(CG * T * HW);
    float sum = g_stats[2 * (b * G + g)];
    float sq  = g_stats[2 * (b * G + g) + 1];
    float mean = sum / n;
    float var  = sq / n - mean * mean;
    float rstd = rsqrtf(var + EPS);
    float a = rstd * scale[c];
    float d = bias[c] - mean * a;

    float4 v = reinterpret_cast<const float4*>(x)[((size_t)(t * B + b) * C + c) * (HW / 4) + p4];
    float4 o = make_float4(v.x * a + d, v.y * a + d, v.z * a + d, v.w * a + d);
    reinterpret_cast<float4*>(g_hn)[i] = o;
}

// ---------------------------------------------------------------------------
// SGEMM: C[m,n] = alpha * sum_k A'(k,m) * B'(k,n) (+ bias[m]) (+ skip[m,n])
// TA/TB: operand stored [X][K] (transposed load) vs [K][X] (direct load).
// 128x128 tile, BK=8, 256 threads, 8x8 microtile, double-buffered smem.
// All dims must divide evenly (they do for this problem).
// ---------------------------------------------------------------------------
template <bool TA, bool TB, bool HAS_BIAS, bool HAS_SKIP>
__global__ __launch_bounds__(256, 2)
void sgemm_kernel(const float* __restrict__ A, int lda, long long sA,
                  const float* __restrict__ Bm, int ldb, long long sB,
                  float* __restrict__ Cm, int ldc, long long sC,
                  int K, float alpha,
                  const float* __restrict__ bias,
                  const float* __restrict__ skip, int ldsk, long long sSk) {
    const int bz = blockIdx.z;
    A  += (size_t)bz * sA;
    Bm += (size_t)bz * sB;
    Cm += (size_t)bz * sC;
    if (HAS_SKIP) skip += (size_t)bz * sSk;

    const int bm = blockIdx.x * 128, bn = blockIdx.y * 128;
    __shared__ float As[2][8][128];
    __shared__ float Bs[2][8][128];
    const int tid = threadIdx.x;

    const int dkr = tid >> 5, dm4 = (tid & 31) << 2;  // direct:   k-row, m-col*4
    const int tm  = tid >> 1, tkq = (tid & 1) << 2;   // trans:    m-row, k-col*4

    float acc[8][8];
    #pragma unroll
    for (int i = 0; i < 8; i++)
        #pragma unroll
        for (int j = 0; j < 8; j++) acc[i][j] = 0.f;

    auto ldgA = [&](int k0) -> float4 {
        if (TA) return *reinterpret_cast<const float4*>(&A[(size_t)(bm + tm) * lda + k0 + tkq]);
        else    return *reinterpret_cast<const float4*>(&A[(size_t)(k0 + dkr) * lda + bm + dm4]);
    };
    auto ldgB = [&](int k0) -> float4 {
        if (TB) return *reinterpret_cast<const float4*>(&Bm[(size_t)(bn + tm) * ldb + k0 + tkq]);
        else    return *reinterpret_cast<const float4*>(&Bm[(size_t)(k0 + dkr) * ldb + bn + dm4]);
    };
    auto stsA = [&](float4 v, int buf) {
        if (TA) {
            As[buf][tkq + 0][tm] = v.x; As[buf][tkq + 1][tm] = v.y;
            As[buf][tkq + 2][tm] = v.z; As[buf][tkq + 3][tm] = v.w;
        } else {
            *reinterpret_cast<float4*>(&As[buf][dkr][dm4]) = v;
        }
    };
    auto stsB = [&](float4 v, int buf) {
        if (TB) {
            Bs[buf][tkq + 0][tm] = v.x; Bs[buf][tkq + 1][tm] = v.y;
            Bs[buf][tkq + 2][tm] = v.z; Bs[buf][tkq + 3][tm] = v.w;
        } else {
            *reinterpret_cast<float4*>(&Bs[buf][dkr][dm4]) = v;
        }
    };

    float4 pa = ldgA(0), pb = ldgB(0);
    stsA(pa, 0); stsB(pb, 0);
    __syncthreads();

    const int nk = K >> 3;
    const int tx = tid & 15, ty = tid >> 4;
    for (int kt = 0; kt < nk; kt++) {
        const int cur = kt & 1;
        const bool pre = (kt + 1 < nk);
        if (pre) { pa = ldgA((kt + 1) << 3); pb = ldgB((kt + 1) << 3); }
        #pragma unroll
        for (int k = 0; k < 8; k++) {
            float4 a0 = *reinterpret_cast<const float4*>(&As[cur][k][ty << 2]);
            float4 a1 = *reinterpret_cast<const float4*>(&As[cur][k][64 + (ty << 2)]);
            float4 b0 = *reinterpret_cast<const float4*>(&Bs[cur][k][tx << 2]);
            float4 b1 = *reinterpret_cast<const float4*>(&Bs[cur][k][64 + (tx << 2)]);
            float av[8] = {a0.x, a0.y, a0.z, a0.w, a1.x, a1.y, a1.z, a1.w};
            float bv[8] = {b0.x, b0.y, b0.z, b0.w, b1.x, b1.y, b1.z, b1.w};
            #pragma unroll
            for (int i = 0; i < 8; i++)
                #pragma unroll
                for (int j = 0; j < 8; j++)
                    acc[i][j] = fmaf(av[i], bv[j], acc[i][j]);
        }
        if (pre) { stsA(pa, cur ^ 1); stsB(pb, cur ^ 1); }
        __syncthreads();
    }

    #pragma unroll
    for (int i = 0; i < 8; i++) {
        int row = bm + ((i < 4) ? (ty * 4 + i) : (64 + ty * 4 + i - 4));
        float bvv = HAS_BIAS ? bias[row] : 0.f;
        #pragma unroll
        for (int jh = 0; jh < 2; jh++) {
            int col = bn + jh * 64 + tx * 4;
            float4 o;
            o.x = fmaf(acc[i][jh * 4 + 0], alpha, bvv);
            o.y = fmaf(acc[i][jh * 4 + 1], alpha, bvv);
            o.z = fmaf(acc[i][jh * 4 + 2], alpha, bvv);
            o.w = fmaf(acc[i][jh * 4 + 3], alpha, bvv);
            if (HAS_SKIP) {
                float4 s = *reinterpret_cast<const float4*>(&skip[(size_t)row * ldsk + col]);
                o.x += s.x; o.y += s.y; o.z += s.z; o.w += s.w;
            }
            *reinterpret_cast<float4*>(&Cm[(size_t)row * ldc + col]) = o;
        }
    }
}

// ---------------------------------------------------------------------------
// Row softmax over 6912 elements; one block per row, values kept in registers.
// ---------------------------------------------------------------------------
__global__ void softmax_kernel(float* __restrict__ sc) {
    __shared__ float red[8];
    __shared__ float bmax, bsum;
    const int tid = threadIdx.x;
    float* row = sc + (size_t)blockIdx.x * N3;

    float vals[27];
    float mx = -1e30f;
    #pragma unroll
    for (int i = 0; i < 27; i++) {
        vals[i] = row[i * 256 + tid];
        mx = fmaxf(mx, vals[i]);
    }
    #pragma unroll
    for (int o = 16; o; o >>= 1) mx = fmaxf(mx, __shfl_xor_sync(0xffffffffu, mx, o));
    if ((tid & 31) == 0) red[tid >> 5] = mx;
    __syncthreads();
    if (tid < 32) {
        float t = (tid < 8) ? red[tid] : -1e30f;
        #pragma unroll
        for (int o = 4; o; o >>= 1) t = fmaxf(t, __shfl_xor_sync(0xffffffffu, t, o));
        if (tid == 0) bmax = t;
    }
    __syncthreads();
    mx = bmax;

    float s = 0.f;
    #pragma unroll
    for (int i = 0; i < 27; i++) { vals[i] = __expf(vals[i] - mx); s += vals[i]; }
    #pragma unroll
    for (int o = 16; o; o >>= 1) s += __shfl_xor_sync(0xffffffffu, s, o);
    if ((tid & 31) == 0) red[tid >> 5] = s;
    __syncthreads();
    if (tid < 32) {
        float t = (tid < 8) ? red[tid] : 0.f;
        #pragma unroll
        for (int o = 4; o; o >>= 1) t += __shfl_xor_sync(0xffffffffu, t, o);
        if (tid == 0) bsum = t;
    }
    __syncthreads();
    float inv = 1.f / bsum;
    #pragma unroll
    for (int i = 0; i < 27; i++) row[i * 256 + tid] = vals[i] * inv;
}

// ---------------------------------------------------------------------------
// Launch
// ---------------------------------------------------------------------------
extern "C" void kernel_launch(void* const* d_in, const int* in_sizes, int n_in,
                              void* d_out, int out_size) {
    const float* x   = (const float*)d_in[0];
    const float* nsc = (const float*)d_in[1];
    const float* nbi = (const float*)d_in[2];
    const float* q_w = (const float*)d_in[3];
    const float* q_b = (const float*)d_in[4];
    const float* k_w = (const float*)d_in[5];
    const float* k_b = (const float*)d_in[6];
    const float* v_w = (const float*)d_in[7];
    const float* v_b = (const float*)d_in[8];
    const float* p_w = (const float*)d_in[9];
    const float* p_b = (const float*)d_in[10];
    float* out = (float*)d_out;

    float *hn, *q, *k, *v, *sc, *ao;
    cudaGetSymbolAddress((void**)&hn, g_hn);
    cudaGetSymbolAddress((void**)&q,  g_q);
    cudaGetSymbolAddress((void**)&k,  g_k);
    cudaGetSymbolAddress((void**)&v,  g_v);
    cudaGetSymbolAddress((void**)&sc, g_sc);
    cudaGetSymbolAddress((void**)&ao, g_ao);

    // GroupNorm
    zero_stats_kernel<<<1, 32>>>();
    gn_stats_kernel<<<dim3(B * G, 16), 256>>>(x);
    gn_apply_kernel<<<(B * C * T * HW / 4) / 256, 256>>>(x, nsc, nbi);

    const long long sHn = (long long)C * N3;   // per-batch stride of hn
    const long long sKV = (long long)C * N3;
    const long long sQ  = (long long)C * HW;
    const long long sSc = (long long)HW * N3;

    // k = k_w @ hn + k_b     (o x 6912 per batch)
    sgemm_kernel<true, false, true, false><<<dim3(C / 128, N3 / 128, B), 256>>>(
        k_w, C, 0, hn, N3, sHn, k, N3, sKV, C, 1.f, k_b, nullptr, 0, 0);
    // v = v_w @ hn + v_b
    sgemm_kernel<true, false, true, false><<<dim3(C / 128, N3 / 128, B), 256>>>(
        v_w, C, 0, hn, N3, sHn, v, N3, sKV, C, 1.f, v_b, nullptr, 0, 0);
    // q = q_w @ hn[:, :, t=1] + q_b   (o x 2304 per batch); also serves as skip
    sgemm_kernel<true, false, true, false><<<dim3(C / 128, HW / 128, B), 256>>>(
        q_w, C, 0, hn + HW, N3, sHn, q, HW, sQ, C, 1.f, q_b, nullptr, 0, 0);

    // scores = (q^T k) * C^-0.5   (2304 x 6912 per batch)
    sgemm_kernel<false, false, false, false><<<dim3(HW / 128, N3 / 128, B), 256>>>(
        q, HW, sQ, k, N3, sKV, sc, N3, sSc, C, 0.044194173824159216f,
        nullptr, nullptr, 0, 0);

    softmax_kernel<<<B * HW, 256>>>(sc);

    // ao = v @ attn^T   (512 x 2304 per batch, K = 6912)
    sgemm_kernel<true, true, false, false><<<dim3(C / 128, HW / 128, B), 256>>>(
        v, N3, sKV, sc, N3, sSc, ao, HW, sQ, N3, 1.f, nullptr, nullptr, 0, 0);

    // out = p_w @ ao + p_b + skip(q)
    sgemm_kernel<true, false, true, true><<<dim3(C / 128, HW / 128, B), 256>>>(
        p_w, C, 0, ao, HW, sQ, out, HW, sQ, C, 1.f, p_b, q, HW, sQ);
}

// round 4
// speedup vs baseline: 1.8607x; 1.8577x over previous
#include <cuda_runtime.h>
#include <cstdint>

constexpr int B  = 4;
constexpr int C  = 512;
constexpr int T  = 3;
constexpr int HW = 2304;   // 48*48
constexpr int N3 = 6912;   // 3*HW
constexpr int G  = 4;
constexpr int CG = C / G;  // 128
constexpr float EPS = 1e-6f;

// Scratch
__device__ float g_hnt[(size_t)B * N3 * C];   // normalized, transposed [b][t*HW+p][c]
__device__ float g_qt [(size_t)B * HW * C];   // q transposed [b][p][c] (also skip)
__device__ float g_kt [(size_t)B * N3 * C];   // k transposed [b][m][c]
__device__ float g_v  [(size_t)B * C * N3];   // v [b][c][m]
__device__ float g_sc [(size_t)B * HW * N3];  // scores / attn [b][p][m]
__device__ float g_ot [(size_t)B * HW * C];   // attn out transposed [b][p][c]
__device__ float g_stats[2 * B * G];

__device__ __forceinline__ float f2tf32(float x) {
    float r; asm("cvt.rna.tf32.f32 %0, %1;" : "=f"(r) : "f"(x)); return r;
}
__device__ __forceinline__ void mma_tf32(float* c, const float* a, const float* b) {
    asm volatile("mma.sync.aligned.m16n8k8.row.col.f32.tf32.tf32.f32 "
        "{%0,%1,%2,%3}, {%4,%5,%6,%7}, {%8,%9}, {%0,%1,%2,%3};"
        : "+f"(c[0]), "+f"(c[1]), "+f"(c[2]), "+f"(c[3])
        : "r"(__float_as_uint(a[0])), "r"(__float_as_uint(a[1])),
          "r"(__float_as_uint(a[2])), "r"(__float_as_uint(a[3])),
          "r"(__float_as_uint(b[0])), "r"(__float_as_uint(b[1])));
}

// ---------------------------------------------------------------------------
// GroupNorm
// ---------------------------------------------------------------------------
__global__ void zero_stats_kernel() {
    if (threadIdx.x < 2 * B * G) g_stats[threadIdx.x] = 0.f;
}

__global__ void gn_stats_kernel(const float* __restrict__ x) {
    const int bg = blockIdx.x;
    const int b = bg >> 2, g = bg & 3;
    const int TOT4 = CG * T * HW / 4;
    const int PER  = TOT4 / 16;
    const int start = blockIdx.y * PER;

    float s = 0.f, ss = 0.f;
    for (int i = start + threadIdx.x; i < start + PER; i += blockDim.x) {
        int cl = i / (T * HW / 4);
        int r  = i - cl * (T * HW / 4);
        int t  = r / (HW / 4);
        int p4 = r - t * (HW / 4);
        float4 v = reinterpret_cast<const float4*>(x)[
            ((size_t)(t * B + b) * C + g * CG + cl) * (HW / 4) + p4];
        s  += v.x + v.y + v.z + v.w;
        ss += v.x * v.x + v.y * v.y + v.z * v.z + v.w * v.w;
    }
    __shared__ float rs[8], rss[8];
    #pragma unroll
    for (int o = 16; o; o >>= 1) {
        s  += __shfl_xor_sync(0xffffffffu, s, o);
        ss += __shfl_xor_sync(0xffffffffu, ss, o);
    }
    if ((threadIdx.x & 31) == 0) { rs[threadIdx.x >> 5] = s; rss[threadIdx.x >> 5] = ss; }
    __syncthreads();
    if (threadIdx.x == 0) {
        float a = 0.f, c = 0.f;
        #pragma unroll
        for (int i = 0; i < 8; i++) { a += rs[i]; c += rss[i]; }
        atomicAdd(&g_stats[2 * bg],     a);
        atomicAdd(&g_stats[2 * bg + 1], c);
    }
}

// normalize + affine + transpose -> g_hnt[b][t*HW+p][c]
__global__ void gn_apply_t_kernel(const float* __restrict__ x,
                                  const float* __restrict__ scale,
                                  const float* __restrict__ bias) {
    __shared__ float tile[32][33];
    const int bt = blockIdx.z;
    const int b = bt / T, t = bt - b * T;
    const int p0 = blockIdx.x << 5, c0 = blockIdx.y << 5;
    const int tx = threadIdx.x, ty = threadIdx.y;  // 32 x 8
    const float nrm = 1.f / (float)(CG * T * HW);

    #pragma unroll
    for (int kk = 0; kk < 4; kk++) {
        int c = c0 + ty + kk * 8;
        int g = c >> 7;
        float sum = g_stats[2 * (b * G + g)];
        float sq  = g_stats[2 * (b * G + g) + 1];
        float mean = sum * nrm;
        float var  = sq * nrm - mean * mean;
        float rstd = rsqrtf(var + EPS);
        float a = rstd * scale[c];
        float d = bias[c] - mean * a;
        float v = x[((size_t)(t * B + b) * C + c) * HW + p0 + tx];
        tile[ty + kk * 8][tx] = v * a + d;
    }
    __syncthreads();
    #pragma unroll
    for (int kk = 0; kk < 4; kk++) {
        int p = p0 + ty + kk * 8;
        g_hnt[(size_t)b * N3 * C + (size_t)(t * HW + p) * C + c0 + tx] = tile[tx][ty + kk * 8];
    }
}

// ---------------------------------------------------------------------------
// TF32 mma.sync GEMM: Cm[m,n] = alpha*sum_k A[m,k]*Bm[n,k] (+bias) (+skipT)
// A:[M][K] K-major, Bm:[N][K] K-major. 128x128 tile, BK=32, 8 warps (2x4),
// warp tile 64x32, m16n8k8 tf32 mma. Quad-XOR swizzled smem.
// BIAS_MODE: 0 none, 1 bias[row m], 2 bias[col n]. skip read [n][m].
// ---------------------------------------------------------------------------
template <int BIAS_MODE, bool HAS_SKIP>
__global__ __launch_bounds__(256)
void mma_gemm(const float* __restrict__ A, int lda, long long sA,
              const float* __restrict__ Bm, int ldb, long long sB,
              float* __restrict__ Cm, int ldc, long long sC,
              int K, float alpha, const float* __restrict__ bias,
              const float* __restrict__ skip, int ldsk, long long sSk) {
    __shared__ float As[128 * 32];
    __shared__ float Bs[128 * 32];

    const int bz = blockIdx.z;
    A  += (size_t)bz * sA;
    Bm += (size_t)bz * sB;
    Cm += (size_t)bz * sC;
    if (HAS_SKIP) skip += (size_t)bz * sSk;

    const int bm = blockIdx.x * 128, bn = blockIdx.y * 128;
    const int tid = threadIdx.x, wid = tid >> 5, lane = tid & 31;
    const int wm = wid & 1, wn = wid >> 1;          // warp 2x4
    const int gr = lane >> 2, t4 = lane & 3;        // group row, thread-in-group

    // global->smem mapping: thread -> row r, k-quads q0..q0+3
    const int r  = tid >> 1;
    const int q0 = (tid & 1) * 4;
    const float* Arow = A  + (size_t)(bm + r) * lda;
    const float* Brow = Bm + (size_t)(bn + r) * ldb;
    int stOff[4];
    #pragma unroll
    for (int j = 0; j < 4; j++)
        stOff[j] = r * 32 + (((q0 + j) ^ (r & 7)) << 2);   // quad-XOR swizzle

    float4 ra[4], rb[4];
    auto ldg = [&](int k0) {
        #pragma unroll
        for (int j = 0; j < 4; j++) {
            ra[j] = *reinterpret_cast<const float4*>(Arow + k0 + (q0 + j) * 4);
            rb[j] = *reinterpret_cast<const float4*>(Brow + k0 + (q0 + j) * 4);
        }
    };
    auto sts = [&]() {
        #pragma unroll
        for (int j = 0; j < 4; j++) {
            float4 a = ra[j], b = rb[j];
            a.x = f2tf32(a.x); a.y = f2tf32(a.y); a.z = f2tf32(a.z); a.w = f2tf32(a.w);
            b.x = f2tf32(b.x); b.y = f2tf32(b.y); b.z = f2tf32(b.z); b.w = f2tf32(b.w);
            *reinterpret_cast<float4*>(&As[stOff[j]]) = a;
            *reinterpret_cast<float4*>(&Bs[stOff[j]]) = b;
        }
    };

    float acc[4][4][4];
    #pragma unroll
    for (int i = 0; i < 4; i++)
        #pragma unroll
        for (int j = 0; j < 4; j++)
            #pragma unroll
            for (int q = 0; q < 4; q++) acc[i][j][q] = 0.f;

    const int swz = gr << 2;   // per-thread XOR (row&7 == gr for all frag rows)
    ldg(0); sts(); __syncthreads();

    const int nk = K >> 5;
    for (int kt = 0; kt < nk; kt++) {
        if (kt + 1 < nk) ldg((kt + 1) << 5);
        #pragma unroll
        for (int kk = 0; kk < 4; kk++) {
            const int sc0 = (kk * 8 + t4) ^ swz;
            const int sc1 = sc0 ^ 4;
            float av[4][4], bv[4][2];
            #pragma unroll
            for (int mf = 0; mf < 4; mf++) {
                int r0 = wm * 64 + mf * 16 + gr;
                av[mf][0] = As[r0 * 32 + sc0];
                av[mf][1] = As[(r0 + 8) * 32 + sc0];
                av[mf][2] = As[r0 * 32 + sc1];
                av[mf][3] = As[(r0 + 8) * 32 + sc1];
            }
            #pragma unroll
            for (int nf = 0; nf < 4; nf++) {
                int rbn = wn * 32 + nf * 8 + gr;
                bv[nf][0] = Bs[rbn * 32 + sc0];
                bv[nf][1] = Bs[rbn * 32 + sc1];
            }
            #pragma unroll
            for (int mf = 0; mf < 4; mf++)
                #pragma unroll
                for (int nf = 0; nf < 4; nf++)
                    mma_tf32(acc[mf][nf], av[mf], bv[nf]);
        }
        __syncthreads();
        if (kt + 1 < nk) { sts(); __syncthreads(); }
    }

    // epilogue
    #pragma unroll
    for (int mf = 0; mf < 4; mf++) {
        #pragma unroll
        for (int half = 0; half < 2; half++) {
            int rw = bm + wm * 64 + mf * 16 + gr + half * 8;
            float bvv = (BIAS_MODE == 1) ? bias[rw] : 0.f;
            #pragma unroll
            for (int nf = 0; nf < 4; nf++) {
                int cl = bn + wn * 32 + nf * 8 + t4 * 2;
                float2 o;
                o.x = acc[mf][nf][half * 2 + 0] * alpha + bvv;
                o.y = acc[mf][nf][half * 2 + 1] * alpha + bvv;
                if (BIAS_MODE == 2) { o.x += bias[cl]; o.y += bias[cl + 1]; }
                if (HAS_SKIP) {
                    o.x += skip[(size_t)cl * ldsk + rw];
                    o.y += skip[(size_t)(cl + 1) * ldsk + rw];
                }
                *reinterpret_cast<float2*>(&Cm[(size_t)rw * ldc + cl]) = o;
            }
        }
    }
}

// ---------------------------------------------------------------------------
// FP32 SGEMM (q/skip path). C[m,n] = sum_k A'(k,m)*B'(k,n) (+bias).
// ---------------------------------------------------------------------------
template <bool TA, bool TB, int BIAS_MODE>
__global__ __launch_bounds__(256, 2)
void sgemm_kernel(const float* __restrict__ A, int lda, long long sA,
                  const float* __restrict__ Bm, int ldb, long long sB,
                  float* __restrict__ Cm, int ldc, long long sC,
                  int K, const float* __restrict__ bias) {
    const int bz = blockIdx.z;
    A  += (size_t)bz * sA;
    Bm += (size_t)bz * sB;
    Cm += (size_t)bz * sC;

    const int bm = blockIdx.x * 128, bn = blockIdx.y * 128;
    __shared__ float As[2][8][128];
    __shared__ float Bs[2][8][128];
    const int tid = threadIdx.x;

    const int dkr = tid >> 5, dm4 = (tid & 31) << 2;
    const int tm  = tid >> 1, tkq = (tid & 1) << 2;

    float acc[8][8];
    #pragma unroll
    for (int i = 0; i < 8; i++)
        #pragma unroll
        for (int j = 0; j < 8; j++) acc[i][j] = 0.f;

    auto ldgA = [&](int k0) -> float4 {
        if (TA) return *reinterpret_cast<const float4*>(&A[(size_t)(bm + tm) * lda + k0 + tkq]);
        else    return *reinterpret_cast<const float4*>(&A[(size_t)(k0 + dkr) * lda + bm + dm4]);
    };
    auto ldgB = [&](int k0) -> float4 {
        if (TB) return *reinterpret_cast<const float4*>(&Bm[(size_t)(bn + tm) * ldb + k0 + tkq]);
        else    return *reinterpret_cast<const float4*>(&Bm[(size_t)(k0 + dkr) * ldb + bn + dm4]);
    };
    auto stsA = [&](float4 v, int buf) {
        if (TA) {
            As[buf][tkq + 0][tm] = v.x; As[buf][tkq + 1][tm] = v.y;
            As[buf][tkq + 2][tm] = v.z; As[buf][tkq + 3][tm] = v.w;
        } else {
            *reinterpret_cast<float4*>(&As[buf][dkr][dm4]) = v;
        }
    };
    auto stsB = [&](float4 v, int buf) {
        if (TB) {
            Bs[buf][tkq + 0][tm] = v.x; Bs[buf][tkq + 1][tm] = v.y;
            Bs[buf][tkq + 2][tm] = v.z; Bs[buf][tkq + 3][tm] = v.w;
        } else {
            *reinterpret_cast<float4*>(&Bs[buf][dkr][dm4]) = v;
        }
    };

    float4 pa = ldgA(0), pb = ldgB(0);
    stsA(pa, 0); stsB(pb, 0);
    __syncthreads();

    const int nk = K >> 3;
    const int tx = tid & 15, ty = tid >> 4;
    for (int kt = 0; kt < nk; kt++) {
        const int cur = kt & 1;
        const bool pre = (kt + 1 < nk);
        if (pre) { pa = ldgA((kt + 1) << 3); pb = ldgB((kt + 1) << 3); }
        #pragma unroll
        for (int k = 0; k < 8; k++) {
            float4 a0 = *reinterpret_cast<const float4*>(&As[cur][k][ty << 2]);
            float4 a1 = *reinterpret_cast<const float4*>(&As[cur][k][64 + (ty << 2)]);
            float4 b0 = *reinterpret_cast<const float4*>(&Bs[cur][k][tx << 2]);
            float4 b1 = *reinterpret_cast<const float4*>(&Bs[cur][k][64 + (tx << 2)]);
            float av[8] = {a0.x, a0.y, a0.z, a0.w, a1.x, a1.y, a1.z, a1.w};
            float bv[8] = {b0.x, b0.y, b0.z, b0.w, b1.x, b1.y, b1.z, b1.w};
            #pragma unroll
            for (int i = 0; i < 8; i++)
                #pragma unroll
                for (int j = 0; j < 8; j++)
                    acc[i][j] = fmaf(av[i], bv[j], acc[i][j]);
        }
        if (pre) { stsA(pa, cur ^ 1); stsB(pb, cur ^ 1); }
        __syncthreads();
    }

    #pragma unroll
    for (int i = 0; i < 8; i++) {
        int row = bm + ((i < 4) ? (ty * 4 + i) : (64 + ty * 4 + i - 4));
        float bvv = (BIAS_MODE == 1) ? bias[row] : 0.f;
        #pragma unroll
        for (int jh = 0; jh < 2; jh++) {
            int col = bn + jh * 64 + tx * 4;
            float4 o;
            o.x = acc[i][jh * 4 + 0] + bvv;
            o.y = acc[i][jh * 4 + 1] + bvv;
            o.z = acc[i][jh * 4 + 2] + bvv;
            o.w = acc[i][jh * 4 + 3] + bvv;
            if (BIAS_MODE == 2) {
                float4 bc = *reinterpret_cast<const float4*>(&bias[col]);
                o.x += bc.x; o.y += bc.y; o.z += bc.z; o.w += bc.w;
            }
            *reinterpret_cast<float4*>(&Cm[(size_t)row * ldc + col]) = o;
        }
    }
}

// ---------------------------------------------------------------------------
// Row softmax over 6912 elems; one block per row, register-resident.
// ---------------------------------------------------------------------------
__global__ void softmax_kernel(float* __restrict__ sc) {
    __shared__ float red[8];
    __shared__ float bmax, bsum;
    const int tid = threadIdx.x;
    float* row = sc + (size_t)blockIdx.x * N3;

    float vals[27];
    float mx = -1e30f;
    #pragma unroll
    for (int i = 0; i < 27; i++) {
        vals[i] = row[i * 256 + tid];
        mx = fmaxf(mx, vals[i]);
    }
    #pragma unroll
    for (int o = 16; o; o >>= 1) mx = fmaxf(mx, __shfl_xor_sync(0xffffffffu, mx, o));
    if ((tid & 31) == 0) red[tid >> 5] = mx;
    __syncthreads();
    if (tid < 32) {
        float t = (tid < 8) ? red[tid] : -1e30f;
        #pragma unroll
        for (int o = 4; o; o >>= 1) t = fmaxf(t, __shfl_xor_sync(0xffffffffu, t, o));
        if (tid == 0) bmax = t;
    }
    __syncthreads();
    mx = bmax;

    float s = 0.f;
    #pragma unroll
    for (int i = 0; i < 27; i++) { vals[i] = __expf(vals[i] - mx); s += vals[i]; }
    #pragma unroll
    for (int o = 16; o; o >>= 1) s += __shfl_xor_sync(0xffffffffu, s, o);
    if ((tid & 31) == 0) red[tid >> 5] = s;
    __syncthreads();
    if (tid < 32) {
        float t = (tid < 8) ? red[tid] : 0.f;
        #pragma unroll
        for (int o = 4; o; o >>= 1) t += __shfl_xor_sync(0xffffffffu, t, o);
        if (tid == 0) bsum = t;
    }
    __syncthreads();
    float inv = 1.f / bsum;
    #pragma unroll
    for (int i = 0; i < 27; i++) row[i * 256 + tid] = vals[i] * inv;
}

// ---------------------------------------------------------------------------
// Launch
// ---------------------------------------------------------------------------
extern "C" void kernel_launch(void* const* d_in, const int* in_sizes, int n_in,
                              void* d_out, int out_size) {
    const float* x   = (const float*)d_in[0];
    const float* nsc = (const float*)d_in[1];
    const float* nbi = (const float*)d_in[2];
    const float* q_w = (const float*)d_in[3];
    const float* q_b = (const float*)d_in[4];
    const float* k_w = (const float*)d_in[5];
    const float* k_b = (const float*)d_in[6];
    const float* v_w = (const float*)d_in[7];
    const float* v_b = (const float*)d_in[8];
    const float* p_w = (const float*)d_in[9];
    const float* p_b = (const float*)d_in[10];
    float* out = (float*)d_out;

    float *hnt, *qt, *kt, *v, *sc, *ot;
    cudaGetSymbolAddress((void**)&hnt, g_hnt);
    cudaGetSymbolAddress((void**)&qt,  g_qt);
    cudaGetSymbolAddress((void**)&kt,  g_kt);
    cudaGetSymbolAddress((void**)&v,   g_v);
    cudaGetSymbolAddress((void**)&sc,  g_sc);
    cudaGetSymbolAddress((void**)&ot,  g_ot);

    const long long sHnt = (long long)N3 * C;
    const long long sQt  = (long long)HW * C;
    const long long sKt  = (long long)N3 * C;
    const long long sV   = (long long)C * N3;
    const long long sSc  = (long long)HW * N3;
    const long long sOt  = (long long)HW * C;

    // GroupNorm (+ transpose into hnt)
    zero_stats_kernel<<<1, 32>>>();
    gn_stats_kernel<<<dim3(B * G, 16), 256>>>(x);
    gn_apply_t_kernel<<<dim3(HW / 32, C / 32, B * T), dim3(32, 8)>>>(x, nsc, nbi);

    // qt[p][o] = hnt[t=1][p][:] . q_w[o][:] + q_b[o]   (fp32 — skip path)
    sgemm_kernel<true, true, 2><<<dim3(HW / 128, C / 128, B), 256>>>(
        hnt + (size_t)HW * C, C, sHnt, q_w, C, 0, qt, C, sQt, C, q_b);

    // kt[m][o] = hnt[m][:] . k_w[o][:] + k_b[o]
    mma_gemm<2, false><<<dim3(N3 / 128, C / 128, B), 256>>>(
        hnt, C, sHnt, k_w, C, 0, kt, C, sKt, C, 1.f, k_b, nullptr, 0, 0);

    // v[c][m] = v_w[c][:] . hnt[m][:] + v_b[c]
    mma_gemm<1, false><<<dim3(C / 128, N3 / 128, B), 256>>>(
        v_w, C, 0, hnt, C, sHnt, v, N3, sV, C, 1.f, v_b, nullptr, 0, 0);

    // scores[p][m] = (qt[p][:] . kt[m][:]) * C^-0.5
    mma_gemm<0, false><<<dim3(HW / 128, N3 / 128, B), 256>>>(
        qt, C, sQt, kt, C, sKt, sc, N3, sSc, C, 0.044194173824159216f,
        nullptr, nullptr, 0, 0);

    softmax_kernel<<<B * HW, 256>>>(sc);

    // ot[p][c] = attn[p][:] . v[c][:]
    mma_gemm<0, false><<<dim3(HW / 128, C / 128, B), 256>>>(
        sc, N3, sSc, v, N3, sV, ot, C, sOt, N3, 1.f, nullptr, nullptr, 0, 0);

    // out[o][p] = p_w[o][:] . ot[p][:] + p_b[o] + qt[p][o]
    mma_gemm<1, true><<<dim3(C / 128, HW / 128, B), 256>>>(
        p_w, C, 0, ot, C, sOt, out, HW, (long long)C * HW, C, 1.f, p_b,
        qt, C, sQt);
}

// round 5
// speedup vs baseline: 2.2215x; 1.1939x over previous
#include <cuda_runtime.h>
#include <cstdint>

constexpr int B  = 4;
constexpr int C  = 512;
constexpr int T  = 3;
constexpr int HW = 2304;   // 48*48
constexpr int N3 = 6912;   // 3*HW
constexpr int G  = 4;
constexpr int CG = C / G;  // 128
constexpr float EPS = 1e-6f;

// Scratch
__device__ float g_hnt[(size_t)B * N3 * C];   // normalized, transposed [b][t*HW+p][c]
__device__ float g_qt [(size_t)B * HW * C];   // q transposed [b][p][c] (also skip)
__device__ float g_kt [(size_t)B * N3 * C];   // k transposed [b][m][c]
__device__ float g_v  [(size_t)B * C * N3];   // v [b][c][m]
__device__ float g_sc [(size_t)B * HW * N3];  // scores / attn [b][p][m]
__device__ float g_ot [(size_t)B * HW * C];   // attn out transposed [b][p][c]
__device__ float g_stats[2 * B * G];

__device__ __forceinline__ uint32_t smem_u32(const void* p) {
    return (uint32_t)__cvta_generic_to_shared(p);
}
#define CP_ASYNC16(sm, gm) \
    asm volatile("cp.async.ca.shared.global [%0], [%1], 16;" :: "r"(sm), "l"(gm))
#define CP_COMMIT asm volatile("cp.async.commit_group;")
#define CP_WAIT1  asm volatile("cp.async.wait_group 1;")
#define CP_WAIT0  asm volatile("cp.async.wait_group 0;")

__device__ __forceinline__ void ldm_x4(uint32_t* r, uint32_t addr) {
    asm volatile("ldmatrix.sync.aligned.m8n8.x4.shared.b16 {%0,%1,%2,%3}, [%4];"
        : "=r"(r[0]), "=r"(r[1]), "=r"(r[2]), "=r"(r[3]) : "r"(addr));
}
__device__ __forceinline__ void mma_tf32(float* c, const uint32_t* a, const uint32_t* b) {
    asm volatile("mma.sync.aligned.m16n8k8.row.col.f32.tf32.tf32.f32 "
        "{%0,%1,%2,%3}, {%4,%5,%6,%7}, {%8,%9}, {%0,%1,%2,%3};"
        : "+f"(c[0]), "+f"(c[1]), "+f"(c[2]), "+f"(c[3])
        : "r"(a[0]), "r"(a[1]), "r"(a[2]), "r"(a[3]), "r"(b[0]), "r"(b[1]));
}

// ---------------------------------------------------------------------------
// GroupNorm
// ---------------------------------------------------------------------------
__global__ void zero_stats_kernel() {
    if (threadIdx.x < 2 * B * G) g_stats[threadIdx.x] = 0.f;
}

__global__ void gn_stats_kernel(const float* __restrict__ x) {
    const int bg = blockIdx.x;
    const int b = bg >> 2, g = bg & 3;
    const int TOT4 = CG * T * HW / 4;
    const int PER  = TOT4 / 16;
    const int start = blockIdx.y * PER;

    float s = 0.f, ss = 0.f;
    for (int i = start + threadIdx.x; i < start + PER; i += blockDim.x) {
        int cl = i / (T * HW / 4);
        int r  = i - cl * (T * HW / 4);
        int t  = r / (HW / 4);
        int p4 = r - t * (HW / 4);
        float4 v = reinterpret_cast<const float4*>(x)[
            ((size_t)(t * B + b) * C + g * CG + cl) * (HW / 4) + p4];
        s  += v.x + v.y + v.z + v.w;
        ss += v.x * v.x + v.y * v.y + v.z * v.z + v.w * v.w;
    }
    __shared__ float rs[8], rss[8];
    #pragma unroll
    for (int o = 16; o; o >>= 1) {
        s  += __shfl_xor_sync(0xffffffffu, s, o);
        ss += __shfl_xor_sync(0xffffffffu, ss, o);
    }
    if ((threadIdx.x & 31) == 0) { rs[threadIdx.x >> 5] = s; rss[threadIdx.x >> 5] = ss; }
    __syncthreads();
    if (threadIdx.x == 0) {
        float a = 0.f, c = 0.f;
        #pragma unroll
        for (int i = 0; i < 8; i++) { a += rs[i]; c += rss[i]; }
        atomicAdd(&g_stats[2 * bg],     a);
        atomicAdd(&g_stats[2 * bg + 1], c);
    }
}

// normalize + affine + transpose -> g_hnt[b][t*HW+p][c]
__global__ void gn_apply_t_kernel(const float* __restrict__ x,
                                  const float* __restrict__ scale,
                                  const float* __restrict__ bias) {
    __shared__ float tile[32][33];
    const int bt = blockIdx.z;
    const int b = bt / T, t = bt - b * T;
    const int p0 = blockIdx.x << 5, c0 = blockIdx.y << 5;
    const int tx = threadIdx.x, ty = threadIdx.y;  // 32 x 8
    const float nrm = 1.f / (float)(CG * T * HW);

    #pragma unroll
    for (int kk = 0; kk < 4; kk++) {
        int c = c0 + ty + kk * 8;
        int g = c >> 7;
        float sum = g_stats[2 * (b * G + g)];
        float sq  = g_stats[2 * (b * G + g) + 1];
        float mean = sum * nrm;
        float var  = sq * nrm - mean * mean;
        float rstd = rsqrtf(var + EPS);
        float a = rstd * scale[c];
        float d = bias[c] - mean * a;
        float v = x[((size_t)(t * B + b) * C + c) * HW + p0 + tx];
        tile[ty + kk * 8][tx] = v * a + d;
    }
    __syncthreads();
    #pragma unroll
    for (int kk = 0; kk < 4; kk++) {
        int p = p0 + ty + kk * 8;
        g_hnt[(size_t)b * N3 * C + (size_t)(t * HW + p) * C + c0 + tx] = tile[tx][ty + kk * 8];
    }
}

// ---------------------------------------------------------------------------
// TF32 mma.sync GEMM with cp.async double-buffering + ldmatrix.
// Cm[m,n] = alpha * sum_k A[m,k]*Bm[n,k] (+bias) (+skip^T)
// A:[M][K] K-major, Bm:[N][K] K-major. 128x128 tile, BK=32, 8 warps (2x4),
// warp tile 64x32. Quad-XOR swizzled smem (conflict-free 16B rows).
// BIAS_MODE: 0 none, 1 bias[row m], 2 bias[col n]. skip read [n][m].
// ---------------------------------------------------------------------------
template <int BIAS_MODE, bool HAS_SKIP>
__global__ __launch_bounds__(256)
void mma_gemm(const float* __restrict__ A, int lda, long long sA,
              const float* __restrict__ Bm, int ldb, long long sB,
              float* __restrict__ Cm, int ldc, long long sC,
              int K, float alpha, const float* __restrict__ bias,
              const float* __restrict__ skip, int ldsk, long long sSk) {
    __shared__ __align__(16) float As[2][128 * 32];
    __shared__ __align__(16) float Bs[2][128 * 32];

    const int bz = blockIdx.z;
    A  += (size_t)bz * sA;
    Bm += (size_t)bz * sB;
    Cm += (size_t)bz * sC;
    if (HAS_SKIP) skip += (size_t)bz * sSk;

    const int bm = blockIdx.x * 128, bn = blockIdx.y * 128;
    const int tid = threadIdx.x, wid = tid >> 5, lane = tid & 31;
    const int wm = wid & 1, wn = wid >> 1;      // warp grid 2x4
    const int gr = lane >> 2, t4 = lane & 3;
    const int grp = lane >> 3, rowin = lane & 7;
    const int qhiA = grp >> 1;                  // A: lanes 0-15 even chunk, 16-31 odd
    const int qhiB = grp & 1;                   // B: alternate per 8 lanes

    // --- gmem -> smem staging (cp.async), thread -> row r, 4 16B chunks ---
    const int r  = tid >> 1;
    const int q0 = (tid & 1) * 4;
    const float* Arow = A  + (size_t)(bm + r) * lda;
    const float* Brow = Bm + (size_t)(bn + r) * ldb;
    uint32_t aSt[2][4], bSt[2][4];
    #pragma unroll
    for (int bf = 0; bf < 2; bf++) {
        uint32_t ab = smem_u32(As[bf]), bb = smem_u32(Bs[bf]);
        #pragma unroll
        for (int j = 0; j < 4; j++) {
            uint32_t off = (r * 32 + (((q0 + j) ^ (r & 7)) << 2)) * 4;
            aSt[bf][j] = ab + off;
            bSt[bf][j] = bb + off;
        }
    }
    auto stage = [&](int k0, int bf) {
        #pragma unroll
        for (int j = 0; j < 4; j++) {
            CP_ASYNC16(aSt[bf][j], Arow + k0 + (q0 + j) * 4);
            CP_ASYNC16(bSt[bf][j], Brow + k0 + (q0 + j) * 4);
        }
        CP_COMMIT;
    };

    // --- fragment row byte-offsets (constant across k) ---
    uint32_t aRow[4], bRow[2];
    #pragma unroll
    for (int mf = 0; mf < 4; mf++)
        aRow[mf] = (uint32_t)(wm * 64 + mf * 16 + (grp & 1) * 8 + rowin) * 128;
    #pragma unroll
    for (int p = 0; p < 2; p++)
        bRow[p] = (uint32_t)(wn * 32 + p * 16 + (grp >> 1) * 8 + rowin) * 128;

    float acc[4][4][4];
    #pragma unroll
    for (int i = 0; i < 4; i++)
        #pragma unroll
        for (int j = 0; j < 4; j++)
            #pragma unroll
            for (int q = 0; q < 4; q++) acc[i][j][q] = 0.f;

    stage(0, 0);
    const int nk = K >> 5;
    for (int kt = 0; kt < nk; kt++) {
        if (kt + 1 < nk) { stage((kt + 1) << 5, (kt + 1) & 1); CP_WAIT1; }
        else             { CP_WAIT0; }
        __syncthreads();
        const uint32_t aB = smem_u32(As[kt & 1]);
        const uint32_t bB = smem_u32(Bs[kt & 1]);
        #pragma unroll
        for (int kk = 0; kk < 4; kk++) {
            uint32_t av[4][4], bv[4][2];
            #pragma unroll
            for (int mf = 0; mf < 4; mf++)
                ldm_x4(av[mf], aB + aRow[mf] + ((((kk << 1) + qhiA) ^ rowin) << 4));
            #pragma unroll
            for (int p = 0; p < 2; p++) {
                uint32_t t[4];
                ldm_x4(t, bB + bRow[p] + ((((kk << 1) + qhiB) ^ rowin) << 4));
                bv[2 * p][0] = t[0]; bv[2 * p][1] = t[1];
                bv[2 * p + 1][0] = t[2]; bv[2 * p + 1][1] = t[3];
            }
            #pragma unroll
            for (int mf = 0; mf < 4; mf++)
                #pragma unroll
                for (int nf = 0; nf < 4; nf++)
                    mma_tf32(acc[mf][nf], av[mf], bv[nf]);
        }
        __syncthreads();
    }

    // epilogue
    #pragma unroll
    for (int mf = 0; mf < 4; mf++) {
        #pragma unroll
        for (int half = 0; half < 2; half++) {
            int rw = bm + wm * 64 + mf * 16 + gr + half * 8;
            float bvv = (BIAS_MODE == 1) ? bias[rw] : 0.f;
            #pragma unroll
            for (int nf = 0; nf < 4; nf++) {
                int cl = bn + wn * 32 + nf * 8 + t4 * 2;
                float2 o;
                o.x = acc[mf][nf][half * 2 + 0] * alpha + bvv;
                o.y = acc[mf][nf][half * 2 + 1] * alpha + bvv;
                if (BIAS_MODE == 2) { o.x += bias[cl]; o.y += bias[cl + 1]; }
                if (HAS_SKIP) {
                    o.x += skip[(size_t)cl * ldsk + rw];
                    o.y += skip[(size_t)(cl + 1) * ldsk + rw];
                }
                *reinterpret_cast<float2*>(&Cm[(size_t)rw * ldc + cl]) = o;
            }
        }
    }
}

// ---------------------------------------------------------------------------
// Row softmax over 6912 elems; one block per row, register-resident.
// ---------------------------------------------------------------------------
__global__ void softmax_kernel(float* __restrict__ sc) {
    __shared__ float red[8];
    __shared__ float bmax, bsum;
    const int tid = threadIdx.x;
    float* row = sc + (size_t)blockIdx.x * N3;

    float vals[27];
    float mx = -1e30f;
    #pragma unroll
    for (int i = 0; i < 27; i++) {
        vals[i] = row[i * 256 + tid];
        mx = fmaxf(mx, vals[i]);
    }
    #pragma unroll
    for (int o = 16; o; o >>= 1) mx = fmaxf(mx, __shfl_xor_sync(0xffffffffu, mx, o));
    if ((tid & 31) == 0) red[tid >> 5] = mx;
    __syncthreads();
    if (tid < 32) {
        float t = (tid < 8) ? red[tid] : -1e30f;
        #pragma unroll
        for (int o = 4; o; o >>= 1) t = fmaxf(t, __shfl_xor_sync(0xffffffffu, t, o));
        if (tid == 0) bmax = t;
    }
    __syncthreads();
    mx = bmax;

    float s = 0.f;
    #pragma unroll
    for (int i = 0; i < 27; i++) { vals[i] = __expf(vals[i] - mx); s += vals[i]; }
    #pragma unroll
    for (int o = 16; o; o >>= 1) s += __shfl_xor_sync(0xffffffffu, s, o);
    if ((tid & 31) == 0) red[tid >> 5] = s;
    __syncthreads();
    if (tid < 32) {
        float t = (tid < 8) ? red[tid] : 0.f;
        #pragma unroll
        for (int o = 4; o; o >>= 1) t += __shfl_xor_sync(0xffffffffu, t, o);
        if (tid == 0) bsum = t;
    }
    __syncthreads();
    float inv = 1.f / bsum;
    #pragma unroll
    for (int i = 0; i < 27; i++) row[i * 256 + tid] = vals[i] * inv;
}

// ---------------------------------------------------------------------------
// Launch
// ---------------------------------------------------------------------------
extern "C" void kernel_launch(void* const* d_in, const int* in_sizes, int n_in,
                              void* d_out, int out_size) {
    const float* x   = (const float*)d_in[0];
    const float* nsc = (const float*)d_in[1];
    const float* nbi = (const float*)d_in[2];
    const float* q_w = (const float*)d_in[3];
    const float* q_b = (const float*)d_in[4];
    const float* k_w = (const float*)d_in[5];
    const float* k_b = (const float*)d_in[6];
    const float* v_w = (const float*)d_in[7];
    const float* v_b = (const float*)d_in[8];
    const float* p_w = (const float*)d_in[9];
    const float* p_b = (const float*)d_in[10];
    float* out = (float*)d_out;

    float *hnt, *qt, *kt, *v, *sc, *ot;
    cudaGetSymbolAddress((void**)&hnt, g_hnt);
    cudaGetSymbolAddress((void**)&qt,  g_qt);
    cudaGetSymbolAddress((void**)&kt,  g_kt);
    cudaGetSymbolAddress((void**)&v,   g_v);
    cudaGetSymbolAddress((void**)&sc,  g_sc);
    cudaGetSymbolAddress((void**)&ot,  g_ot);

    const long long sHnt = (long long)N3 * C;
    const long long sQt  = (long long)HW * C;
    const long long sKt  = (long long)N3 * C;
    const long long sV   = (long long)C * N3;
    const long long sSc  = (long long)HW * N3;
    const long long sOt  = (long long)HW * C;

    // GroupNorm (+ transpose into hnt)
    zero_stats_kernel<<<1, 32>>>();
    gn_stats_kernel<<<dim3(B * G, 16), 256>>>(x);
    gn_apply_t_kernel<<<dim3(HW / 32, C / 32, B * T), dim3(32, 8)>>>(x, nsc, nbi);

    // qt[p][o] = hnt[t=1][p][:] . q_w[o][:] + q_b[o]
    mma_gemm<2, false><<<dim3(HW / 128, C / 128, B), 256>>>(
        hnt + (size_t)HW * C, C, sHnt, q_w, C, 0, qt, C, sQt, C, 1.f, q_b,
        nullptr, 0, 0);

    // kt[m][o] = hnt[m][:] . k_w[o][:] + k_b[o]
    mma_gemm<2, false><<<dim3(N3 / 128, C / 128, B), 256>>>(
        hnt, C, sHnt, k_w, C, 0, kt, C, sKt, C, 1.f, k_b, nullptr, 0, 0);

    // v[c][m] = v_w[c][:] . hnt[m][:] + v_b[c]
    mma_gemm<1, false><<<dim3(C / 128, N3 / 128, B), 256>>>(
        v_w, C, 0, hnt, C, sHnt, v, N3, sV, C, 1.f, v_b, nullptr, 0, 0);

    // scores[p][m] = (qt[p][:] . kt[m][:]) * C^-0.5
    mma_gemm<0, false><<<dim3(HW / 128, N3 / 128, B), 256>>>(
        qt, C, sQt, kt, C, sKt, sc, N3, sSc, C, 0.044194173824159216f,
        nullptr, nullptr, 0, 0);

    softmax_kernel<<<B * HW, 256>>>(sc);

    // ot[p][c] = attn[p][:] . v[c][:]
    mma_gemm<0, false><<<dim3(HW / 128, C / 128, B), 256>>>(
        sc, N3, sSc, v, N3, sV, ot, C, sOt, N3, 1.f, nullptr, nullptr, 0, 0);

    // out[o][p] = p_w[o][:] . ot[p][:] + p_b[o] + qt[p][o]
    mma_gemm<1, true><<<dim3(C / 128, HW / 128, B), 256>>>(
        p_w, C, 0, ot, C, sOt, out, HW, (long long)C * HW, C, 1.f, p_b,
        qt, C, sQt);
}